// round 11
// baseline (speedup 1.0000x reference)
#include <cuda_runtime.h>

// Single CTA, 512 threads. Planar smem twiddle tables (mean-removal + MTI folded),
// 2x register blocking per warp in both stages, packed f32x2 FMAs, direct STG epilogue.

typedef unsigned long long u64;

constexpr double PI_D = 3.14159265358979323846264338327950288;

constexpr double d_sin(double x) {
    double t = x, s = x, x2 = x * x;
    for (int n = 1; n <= 11; ++n) { t *= -x2 / double((2*n)*(2*n+1)); s += t; }
    return s;
}
constexpr double d_cos(double x) {
    double t = 1.0, s = 1.0, x2 = x * x;
    for (int n = 1; n <= 11; ++n) { t *= -x2 / double((2*n-1)*(2*n)); s += t; }
    return s;
}
constexpr double d_sqrt(double x) {
    if (x <= 0.0) return 0.0;
    double r = x > 1.0 ? x : 1.0;
    for (int i = 0; i < 40; ++i) r = 0.5 * (r + x / r);
    return r;
}
constexpr double d_i0(double x) {
    double t = 1.0, s = 1.0, q = x * 0.5;
    for (int m = 1; m <= 70; ++m) { double u = q / m; t *= u * u; s += t; }
    return s;
}
constexpr double red(double a) {
    while (a < -PI_D) a += 2.0 * PI_D;
    while (a >  PI_D) a -= 2.0 * PI_D;
    return a;
}

struct alignas(16) Tab {
    float t1r[32][64];   // [k][s]: Re(rw[s]*e^{-2pi i ks/64}) - RKr[k]/64
    float t1i[32][64];
    float t2r[32][32];   // [d][c]: Re(dw[c]*e^{-2pi i dc/32}) - WDr[d]/32
    float t2i[32][32];
};
#define TAB_F4 1536      // 24KB / 16

constexpr Tab make_tab() {
    Tab T{};
    double rw[64] = {}; double rsum = 0.0;
    for (int n = 0; n < 64; ++n) { rw[n] = 0.5 - 0.5 * d_cos(red(2.0*PI_D*n/63.0)); rsum += rw[n]; }
    for (int n = 0; n < 64; ++n) rw[n] /= rsum;
    double dw[32] = {}; double dsum = 0.0; double i025 = d_i0(25.0);
    for (int n = 0; n < 32; ++n) {
        double al = 15.5, tt = (n - al) / al, arg = 1.0 - tt*tt;
        dw[n] = d_i0(25.0 * d_sqrt(arg < 0.0 ? 0.0 : arg)) / i025; dsum += dw[n];
    }
    for (int n = 0; n < 32; ++n) dw[n] /= dsum;
    for (int k = 0; k < 32; ++k) {
        double rkr = 0.0, rki = 0.0;
        for (int s = 0; s < 64; ++s) {
            double ang = red(-2.0*PI_D*double((k*s)&63)/64.0);
            rkr += rw[s]*d_cos(ang); rki += rw[s]*d_sin(ang);
        }
        for (int s = 0; s < 64; ++s) {
            double ang = red(-2.0*PI_D*double((k*s)&63)/64.0);
            T.t1r[k][s] = (float)(rw[s]*d_cos(ang) - rkr/64.0);
            T.t1i[k][s] = (float)(rw[s]*d_sin(ang) - rki/64.0);
        }
    }
    for (int d = 0; d < 32; ++d) {
        double wdr = 0.0, wdi = 0.0;
        for (int c = 0; c < 32; ++c) {
            double ang = red(-2.0*PI_D*double((d*c)&31)/32.0);
            wdr += dw[c]*d_cos(ang); wdi += dw[c]*d_sin(ang);
        }
        for (int c = 0; c < 32; ++c) {
            double ang = red(-2.0*PI_D*double((d*c)&31)/32.0);
            T.t2r[d][c] = (float)(dw[c]*d_cos(ang) - wdr/32.0);
            T.t2i[d][c] = (float)(dw[c]*d_sin(ang) - wdi/32.0);
        }
    }
    return T;
}

__device__ const Tab g_tab = make_tab();

__device__ __forceinline__ void upk(u64 v, float& lo, float& hi) {
    asm("mov.b64 {%0,%1}, %2;" : "=f"(lo), "=f"(hi) : "l"(v));
}
__device__ __forceinline__ u64 ffma2(u64 a, u64 b, u64 c) {
    u64 d; asm("fma.rn.f32x2 %0, %1, %2, %3;" : "=l"(d) : "l"(a), "l"(b), "l"(c)); return d;
}
__device__ __forceinline__ float psum(u64 v) { float lo, hi; upk(v, lo, hi); return lo + hi; }

// x pitch 68 floats (16B-stride 17, odd -> LDS.128 conflict-free)
// X pitch 36 floats (16B-stride 9, odd)
#define XP 68
#define KP 36

__global__ __launch_bounds__(512) void rdm_kernel(const float* __restrict__ frame,
                                                  float* __restrict__ out)
{
    __shared__ __align__(16) float s_tab[TAB_F4 * 4];   // 24KB planar tables
    __shared__ __align__(16) float s_x[32 * XP];        // [c][s]
    __shared__ __align__(16) float s_Xr[32 * KP];       // [k][c]
    __shared__ __align__(16) float s_Xi[32 * KP];

    const int tid  = threadIdx.x;
    const int lane = tid & 31;
    const int warp = tid >> 5;

    // ---- staging: all threads move tables (3 f4 each); threads 0..511 also frame ----
    {
        const float4* src = (const float4*)&g_tab;
        float4* dst = (float4*)s_tab;
        #pragma unroll
        for (int i = 0; i < 3; ++i) dst[tid + i * 512] = src[tid + i * 512];
        float4 fv = ((const float4*)frame)[tid];          // frame[0]: 512 float4
        int c = tid >> 4, s4 = (tid & 15) << 2;
        *(float4*)(s_x + c * XP + s4) = fv;
    }
    __syncthreads();

    const float* T1r = s_tab;
    const float* T1i = s_tab + 2048;
    const float* T2r = s_tab + 4096;
    const float* T2i = s_tab + 5120;

    // ---- stage 1: range DFT. warp -> k = {2w, 2w+1}; lane = c ----
    {
        const int c = lane, k2 = warp << 1;
        const float* xrow = s_x + c * XP;
        const float* tr0 = T1r + (k2 + 0) * 64;
        const float* ti0 = T1i + (k2 + 0) * 64;
        const float* tr1 = T1r + (k2 + 1) * 64;
        const float* ti1 = T1i + (k2 + 1) * 64;
        u64 ar0 = 0, ai0 = 0, ar1 = 0, ai1 = 0;
        #pragma unroll
        for (int s = 0; s < 64; s += 4) {
            ulonglong2 xv = *(const ulonglong2*)(xrow + s);   // (x0,x1),(x2,x3)
            ulonglong2 a0 = *(const ulonglong2*)(tr0 + s);    // broadcasts
            ulonglong2 b0 = *(const ulonglong2*)(ti0 + s);
            ulonglong2 a1 = *(const ulonglong2*)(tr1 + s);
            ulonglong2 b1 = *(const ulonglong2*)(ti1 + s);
            ar0 = ffma2(xv.x, a0.x, ar0); ar0 = ffma2(xv.y, a0.y, ar0);
            ai0 = ffma2(xv.x, b0.x, ai0); ai0 = ffma2(xv.y, b0.y, ai0);
            ar1 = ffma2(xv.x, a1.x, ar1); ar1 = ffma2(xv.y, a1.y, ar1);
            ai1 = ffma2(xv.x, b1.x, ai1); ai1 = ffma2(xv.y, b1.y, ai1);
        }
        s_Xr[(k2 + 0) * KP + c] = psum(ar0);
        s_Xi[(k2 + 0) * KP + c] = psum(ai0);
        s_Xr[(k2 + 1) * KP + c] = psum(ar1);
        s_Xi[(k2 + 1) * KP + c] = psum(ai1);
    }
    __syncthreads();

    // ---- stage 2: doppler DFT (+folded MTI) + epilogue. warp -> d = {2w,2w+1}; lane = k ----
    {
        const int k = lane, d2 = warp << 1;
        const float* xrp = s_Xr + k * KP;
        const float* xip = s_Xi + k * KP;
        const float* ta0 = T2r + (d2 + 0) * 32;
        const float* tb0 = T2i + (d2 + 0) * 32;
        const float* ta1 = T2r + (d2 + 1) * 32;
        const float* tb1 = T2i + (d2 + 1) * 32;
        u64 A0 = 0, B0 = 0, C0 = 0, D0 = 0;   // Σxr*a, Σxi*b, Σxr*b, Σxi*a  (d2+0)
        u64 A1 = 0, B1 = 0, C1 = 0, D1 = 0;   // (d2+1)
        #pragma unroll
        for (int c = 0; c < 32; c += 4) {
            ulonglong2 xr2 = *(const ulonglong2*)(xrp + c);
            ulonglong2 xi2 = *(const ulonglong2*)(xip + c);
            ulonglong2 a0  = *(const ulonglong2*)(ta0 + c);   // broadcasts
            ulonglong2 b0  = *(const ulonglong2*)(tb0 + c);
            ulonglong2 a1  = *(const ulonglong2*)(ta1 + c);
            ulonglong2 b1  = *(const ulonglong2*)(tb1 + c);
            A0 = ffma2(xr2.x, a0.x, A0); A0 = ffma2(xr2.y, a0.y, A0);
            B0 = ffma2(xi2.x, b0.x, B0); B0 = ffma2(xi2.y, b0.y, B0);
            C0 = ffma2(xr2.x, b0.x, C0); C0 = ffma2(xr2.y, b0.y, C0);
            D0 = ffma2(xi2.x, a0.x, D0); D0 = ffma2(xi2.y, a0.y, D0);
            A1 = ffma2(xr2.x, a1.x, A1); A1 = ffma2(xr2.y, a1.y, A1);
            B1 = ffma2(xi2.x, b1.x, B1); B1 = ffma2(xi2.y, b1.y, B1);
            C1 = ffma2(xr2.x, b1.x, C1); C1 = ffma2(xr2.y, b1.y, C1);
            D1 = ffma2(xi2.x, a1.x, D1); D1 = ffma2(xi2.y, a1.y, D1);
        }
        // pixel (d, k) -> out[(31-k)*32 + ((d+16)&31)], written directly (no 3rd barrier)
        {
            float zr = psum(A0) - psum(B0);
            float zi = psum(C0) + psum(D0);
            float mag = sqrtf(zr * zr + zi * zi) * 1000.0f;
            float v = fminf(fmaxf(mag, 0.0f), 1.0f) * 255.0f;
            out[(31 - k) * 32 + ((d2 + 0 + 16) & 31)] = truncf(v);
        }
        {
            float zr = psum(A1) - psum(B1);
            float zi = psum(C1) + psum(D1);
            float mag = sqrtf(zr * zr + zi * zi) * 1000.0f;
            float v = fminf(fmaxf(mag, 0.0f), 1.0f) * 255.0f;
            out[(31 - k) * 32 + ((d2 + 1 + 16) & 31)] = truncf(v);
        }
    }
}

extern "C" void kernel_launch(void* const* d_in, const int* in_sizes, int n_in,
                              void* d_out, int out_size)
{
    (void)in_sizes; (void)n_in; (void)out_size;
    rdm_kernel<<<1, 512>>>((const float*)d_in[0], (float*)d_out);
}

// round 12
// speedup vs baseline: 1.0072x; 1.0072x over previous
#include <cuda_runtime.h>

// Single CTA, 1024 threads, ONE barrier.
// Stage 1 (range DFT): warp = k, lane = c; hann + per-chirp-mean fold baked in table.
// Stage 2 (doppler): warp-local -> MTI via shfl all-reduce, kaiser window,
// 5-stage shfl.bfly DIF FFT across lanes (no smem, no barrier, no T2 table).

typedef unsigned long long u64;

constexpr double PI_D = 3.14159265358979323846264338327950288;

constexpr double d_sin(double x) {
    double t = x, s = x, x2 = x * x;
    for (int n = 1; n <= 11; ++n) { t *= -x2 / double((2*n)*(2*n+1)); s += t; }
    return s;
}
constexpr double d_cos(double x) {
    double t = 1.0, s = 1.0, x2 = x * x;
    for (int n = 1; n <= 11; ++n) { t *= -x2 / double((2*n-1)*(2*n)); s += t; }
    return s;
}
constexpr double d_sqrt(double x) {
    if (x <= 0.0) return 0.0;
    double r = x > 1.0 ? x : 1.0;
    for (int i = 0; i < 40; ++i) r = 0.5 * (r + x / r);
    return r;
}
constexpr double d_i0(double x) {
    double t = 1.0, s = 1.0, q = x * 0.5;
    for (int m = 1; m <= 70; ++m) { double u = q / m; t *= u * u; s += t; }
    return s;
}
constexpr double red(double a) {
    while (a < -PI_D) a += 2.0 * PI_D;
    while (a >  PI_D) a -= 2.0 * PI_D;
    return a;
}

struct alignas(16) Tab1 {
    float t1r[32][64];   // [k][s]: Re(rw[s]*e^{-2pi i ks/64}) - RKr[k]/64  (hann + mean fold)
    float t1i[32][64];
};
struct alignas(16) Small {
    float w32[32][2];    // omega32^j = e^{-2pi i j/32}
    float dw[32];        // kaiser(32, beta=25)/sum
    float pad[32];
};

constexpr Tab1 make_tab1() {
    Tab1 T{};
    double rw[64] = {}; double rsum = 0.0;
    for (int n = 0; n < 64; ++n) { rw[n] = 0.5 - 0.5 * d_cos(red(2.0*PI_D*n/63.0)); rsum += rw[n]; }
    for (int n = 0; n < 64; ++n) rw[n] /= rsum;
    for (int k = 0; k < 32; ++k) {
        double rkr = 0.0, rki = 0.0;
        for (int s = 0; s < 64; ++s) {
            double ang = red(-2.0*PI_D*double((k*s)&63)/64.0);
            rkr += rw[s]*d_cos(ang); rki += rw[s]*d_sin(ang);
        }
        for (int s = 0; s < 64; ++s) {
            double ang = red(-2.0*PI_D*double((k*s)&63)/64.0);
            T.t1r[k][s] = (float)(rw[s]*d_cos(ang) - rkr/64.0);
            T.t1i[k][s] = (float)(rw[s]*d_sin(ang) - rki/64.0);
        }
    }
    return T;
}
constexpr Small make_small() {
    Small S{};
    for (int j = 0; j < 32; ++j) {
        double ang = red(-2.0*PI_D*j/32.0);
        S.w32[j][0] = (float)d_cos(ang);
        S.w32[j][1] = (float)d_sin(ang);
    }
    double dw[32] = {}; double dsum = 0.0; double i025 = d_i0(25.0);
    for (int n = 0; n < 32; ++n) {
        double al = 15.5, tt = (n - al) / al, arg = 1.0 - tt*tt;
        dw[n] = d_i0(25.0 * d_sqrt(arg < 0.0 ? 0.0 : arg)) / i025; dsum += dw[n];
    }
    for (int n = 0; n < 32; ++n) S.dw[n] = (float)(dw[n] / dsum);
    return S;
}

__device__ const Tab1  g_tab1  = make_tab1();
__device__ const Small g_small = make_small();

__device__ __forceinline__ void upk(u64 v, float& lo, float& hi) {
    asm("mov.b64 {%0,%1}, %2;" : "=f"(lo), "=f"(hi) : "l"(v));
}
__device__ __forceinline__ u64 ffma2(u64 a, u64 b, u64 c) {
    u64 d; asm("fma.rn.f32x2 %0, %1, %2, %3;" : "=l"(d) : "l"(a), "l"(b), "l"(c)); return d;
}
__device__ __forceinline__ float psum(u64 v) { float lo, hi; upk(v, lo, hi); return lo + hi; }

#define XP 68   // x row pitch in floats (16B-stride 17, odd -> LDS.128 conflict-free)

__global__ __launch_bounds__(1024) void rdm_kernel(const float* __restrict__ frame,
                                                   float* __restrict__ out)
{
    __shared__ __align__(16) float  s_tab[4096];   // 16KB: t1r | t1i
    __shared__ __align__(16) float  s_x[32 * XP];  // [c][s]
    __shared__ __align__(16) float2 s_w32[32];
    __shared__ __align__(16) float  s_dw[32];

    const int tid  = threadIdx.x;
    const int lane = tid & 31;
    const int warp = tid >> 5;

    // ---- staging (single barrier in whole kernel) ----
    {
        const float4* src = (const float4*)&g_tab1;
        ((float4*)s_tab)[tid] = src[tid];                 // 1024 f4 = 16KB exact
        if (tid < 512) {
            float4 fv = ((const float4*)frame)[tid];      // frame[0]: 2048 floats
            int c = tid >> 4, s4 = (tid & 15) << 2;
            *(float4*)(s_x + c * XP + s4) = fv;
        }
        if (tid < 32) {
            s_w32[tid] = ((const float2*)g_small.w32)[tid];
            s_dw[tid]  = g_small.dw[tid];
        }
    }
    __syncthreads();

    // ---- stage 1: range DFT. warp = k, lane = c. packed even/odd-s partials ----
    float Xr, Xi;
    {
        const int k = warp, c = lane;
        const float* xrow = s_x + c * XP;
        const float* tr = s_tab + k * 64;
        const float* ti = s_tab + 2048 + k * 64;
        u64 ar = 0, ai = 0;
        #pragma unroll
        for (int s = 0; s < 64; s += 4) {
            ulonglong2 xv = *(const ulonglong2*)(xrow + s);   // (x0,x1),(x2,x3)
            ulonglong2 tv = *(const ulonglong2*)(tr + s);     // broadcast
            ulonglong2 uv = *(const ulonglong2*)(ti + s);     // broadcast
            ar = ffma2(xv.x, tv.x, ar);
            ar = ffma2(xv.y, tv.y, ar);
            ai = ffma2(xv.x, uv.x, ai);
            ai = ffma2(xv.y, uv.y, ai);
        }
        Xr = psum(ar);
        Xi = psum(ai);
    }

    // ---- MTI: subtract mean over lanes (chirps) via butterfly all-reduce ----
    {
        float mr = Xr, mi = Xi;
        #pragma unroll
        for (int h = 16; h >= 1; h >>= 1) {
            mr += __shfl_xor_sync(0xFFFFFFFFu, mr, h);
            mi += __shfl_xor_sync(0xFFFFFFFFu, mi, h);
        }
        float w = s_dw[lane];                 // kaiser window
        Xr = (Xr - mr * 0.03125f) * w;
        Xi = (Xi - mi * 0.03125f) * w;
    }

    // ---- 32-pt DIF FFT across lanes (natural in -> bit-reversed out) ----
    float vr = Xr, vi = Xi;
    #pragma unroll
    for (int h = 16; h >= 1; h >>= 1) {
        float tr = __shfl_xor_sync(0xFFFFFFFFu, vr, h);
        float ti = __shfl_xor_sync(0xFFFFFFFFu, vi, h);
        bool up = (lane & h) != 0;
        float2 w2 = s_w32[(lane & (h - 1)) * (16 / h)];   // omega32^{j*16/h}
        float sr = vr + tr,  si = vi + ti;                // lower: A + B
        float dr = tr - vr,  di = ti - vi;                // upper: (A - B)
        float ur = dr * w2.x - di * w2.y;                 //        * twiddle
        float ui = dr * w2.y + di * w2.x;
        vr = up ? ur : sr;
        vi = up ? ui : si;
    }

    // ---- epilogue: lane holds bin d = bitrev5(lane); fftshift -> bitrev5(lane^1) ----
    {
        float mag = sqrtf(vr * vr + vi * vi) * 1000.0f;
        float v = fminf(fmaxf(mag, 0.0f), 1.0f) * 255.0f;
        int m = __brev((unsigned)(lane ^ 1)) >> 27;       // (d+16)&31
        out[(31 - warp) * 32 + m] = truncf(v);            // transpose + flip(range)
    }
}

extern "C" void kernel_launch(void* const* d_in, const int* in_sizes, int n_in,
                              void* d_out, int out_size)
{
    (void)in_sizes; (void)n_in; (void)out_size;
    rdm_kernel<<<1, 1024>>>((const float*)d_in[0], (float*)d_out);
}

// round 15
// speedup vs baseline: 1.3462x; 1.3365x over previous
#include <cuda_runtime.h>

// 32 CTAs x 32 threads (one warp per range bin k). No smem, no barriers.
// Warp k: lane c holds chirp row c in registers; stage-1 range DFT uses
// warp-uniform twiddle broadcasts; MTI + kaiser + 32-pt doppler FFT via shfl.

typedef unsigned long long u64;

constexpr double PI_D = 3.14159265358979323846264338327950288;

constexpr double d_sin(double x) {
    double t = x, s = x, x2 = x * x;
    for (int n = 1; n <= 11; ++n) { t *= -x2 / double((2*n)*(2*n+1)); s += t; }
    return s;
}
constexpr double d_cos(double x) {
    double t = 1.0, s = 1.0, x2 = x * x;
    for (int n = 1; n <= 11; ++n) { t *= -x2 / double((2*n-1)*(2*n)); s += t; }
    return s;
}
constexpr double d_sqrt(double x) {
    if (x <= 0.0) return 0.0;
    double r = x > 1.0 ? x : 1.0;
    for (int i = 0; i < 40; ++i) r = 0.5 * (r + x / r);
    return r;
}
constexpr double d_i0(double x) {
    double t = 1.0, s = 1.0, q = x * 0.5;
    for (int m = 1; m <= 70; ++m) { double u = q / m; t *= u * u; s += t; }
    return s;
}
constexpr double red(double a) {
    while (a < -PI_D) a += 2.0 * PI_D;
    while (a >  PI_D) a -= 2.0 * PI_D;
    return a;
}

struct alignas(16) Tab1 {
    float t1r[32][64];   // [k][s]: Re(rw[s]*e^{-2pi i ks/64}) - RKr[k]/64  (hann + mean fold)
    float t1i[32][64];
};
struct alignas(16) Small {
    float w32r[32];      // Re(e^{-2pi i j/32})
    float w32i[32];
    float dw[32];        // kaiser(32,25)/sum
    float pad[32];
};

constexpr Tab1 make_tab1() {
    Tab1 T{};
    double rw[64] = {}; double rsum = 0.0;
    for (int n = 0; n < 64; ++n) { rw[n] = 0.5 - 0.5 * d_cos(red(2.0*PI_D*n/63.0)); rsum += rw[n]; }
    for (int n = 0; n < 64; ++n) rw[n] /= rsum;
    for (int k = 0; k < 32; ++k) {
        double rkr = 0.0, rki = 0.0;
        for (int s = 0; s < 64; ++s) {
            double ang = red(-2.0*PI_D*double((k*s)&63)/64.0);
            rkr += rw[s]*d_cos(ang); rki += rw[s]*d_sin(ang);
        }
        for (int s = 0; s < 64; ++s) {
            double ang = red(-2.0*PI_D*double((k*s)&63)/64.0);
            T.t1r[k][s] = (float)(rw[s]*d_cos(ang) - rkr/64.0);
            T.t1i[k][s] = (float)(rw[s]*d_sin(ang) - rki/64.0);
        }
    }
    return T;
}
constexpr Small make_small() {
    Small S{};
    for (int j = 0; j < 32; ++j) {
        double ang = red(-2.0*PI_D*j/32.0);
        S.w32r[j] = (float)d_cos(ang);
        S.w32i[j] = (float)d_sin(ang);
    }
    double dw[32] = {}; double dsum = 0.0; double i025 = d_i0(25.0);
    for (int n = 0; n < 32; ++n) {
        double al = 15.5, tt = (n - al) / al, arg = 1.0 - tt*tt;
        dw[n] = d_i0(25.0 * d_sqrt(arg < 0.0 ? 0.0 : arg)) / i025; dsum += dw[n];
    }
    for (int n = 0; n < 32; ++n) S.dw[n] = (float)(dw[n] / dsum);
    return S;
}

__device__ const Tab1  g_tab1  = make_tab1();
__device__ const Small g_small = make_small();

__device__ __forceinline__ void upk(u64 v, float& lo, float& hi) {
    asm("mov.b64 {%0,%1}, %2;" : "=f"(lo), "=f"(hi) : "l"(v));
}
__device__ __forceinline__ u64 ffma2(u64 a, u64 b, u64 c) {
    u64 d; asm("fma.rn.f32x2 %0, %1, %2, %3;" : "=l"(d) : "l"(a), "l"(b), "l"(c)); return d;
}
__device__ __forceinline__ float psum(u64 v) { float lo, hi; upk(v, lo, hi); return lo + hi; }

__global__ __launch_bounds__(32) void rdm_kernel(const float* __restrict__ frame,
                                                 float* __restrict__ out)
{
    const int lane = threadIdx.x;          // chirp c (stage 1) / FFT lane (stage 2)
    const int k    = blockIdx.x;           // range bin

    // ---- load chirp row c = lane into registers (16 float4, MLP=16) ----
    float4 xv[16];
    {
        const float4* xp = (const float4*)(frame + lane * 64);
        #pragma unroll
        for (int i = 0; i < 16; ++i) xv[i] = xp[i];
    }

    // ---- stage 1: X[k][c] = sum_s x[c][s] * t1[k][s]  (warp-uniform t broadcasts) ----
    float Xr, Xi;
    {
        const ulonglong2* tr = (const ulonglong2*)&g_tab1.t1r[k][0];   // 16 x 16B uniform
        const ulonglong2* ti = (const ulonglong2*)&g_tab1.t1i[k][0];
        u64 ar = 0, ai = 0;
        #pragma unroll
        for (int i = 0; i < 16; ++i) {
            u64 x01, x23;
            asm("mov.b64 %0, {%1,%2};" : "=l"(x01) : "f"(xv[i].x), "f"(xv[i].y));
            asm("mov.b64 %0, {%1,%2};" : "=l"(x23) : "f"(xv[i].z), "f"(xv[i].w));
            ulonglong2 tv = tr[i];
            ulonglong2 uv = ti[i];
            ar = ffma2(x01, tv.x, ar);
            ar = ffma2(x23, tv.y, ar);
            ai = ffma2(x01, uv.x, ai);
            ai = ffma2(x23, uv.y, ai);
        }
        Xr = psum(ar);
        Xi = psum(ai);
    }

    // ---- MTI: subtract mean over lanes (chirps); kaiser window ----
    {
        float mr = Xr, mi = Xi;
        #pragma unroll
        for (int h = 16; h >= 1; h >>= 1) {
            mr += __shfl_xor_sync(0xFFFFFFFFu, mr, h);
            mi += __shfl_xor_sync(0xFFFFFFFFu, mi, h);
        }
        float w = g_small.dw[lane];
        Xr = (Xr - mr * 0.03125f) * w;
        Xi = (Xi - mi * 0.03125f) * w;
    }

    // ---- 32-pt DIF FFT across lanes (natural in -> bit-reversed out) ----
    float vr = Xr, vi = Xi;
    #pragma unroll
    for (int h = 16; h >= 1; h >>= 1) {
        float tr = __shfl_xor_sync(0xFFFFFFFFu, vr, h);
        float ti = __shfl_xor_sync(0xFFFFFFFFu, vi, h);
        bool up = (lane & h) != 0;
        int j = (lane & (h - 1)) * (16 / h);
        float wr = g_small.w32r[j];
        float wi = g_small.w32i[j];
        float sr = vr + tr,  si = vi + ti;    // lower: A + B
        float dr = tr - vr,  di = ti - vi;    // upper: (A - B) * twiddle
        float ur = dr * wr - di * wi;
        float ui = dr * wi + di * wr;
        vr = up ? ur : sr;
        vi = up ? ui : si;
    }

    // ---- epilogue: lane holds bin d = bitrev5(lane); fftshift -> bitrev5(lane^1) ----
    {
        float mag = sqrtf(vr * vr + vi * vi) * 1000.0f;
        float v = fminf(fmaxf(mag, 0.0f), 1.0f) * 255.0f;
        int m = __brev((unsigned)(lane ^ 1)) >> 27;     // (d+16)&31
        out[(31 - k) * 32 + m] = truncf(v);             // one 128B line per CTA
    }
}

extern "C" void kernel_launch(void* const* d_in, const int* in_sizes, int n_in,
                              void* d_out, int out_size)
{
    (void)in_sizes; (void)n_in; (void)out_size;
    rdm_kernel<<<32, 32>>>((const float*)d_in[0], (float*)d_out);
}

// round 16
// speedup vs baseline: 1.3527x; 1.0048x over previous
#include <cuda_runtime.h>

// 32 CTAs x 32 threads (one warp per range bin k). No smem, no barriers.
// Stage 1: lane c holds chirp row c in regs; range DFT vs warp-uniform twiddles.
// Stage 2: kaiser-windowed 32-pt shfl FFT; MTI folded into epilogue
// (FFT((X-m)dw) = FFT(X dw) - m*WD) so the mean-reduce runs interleaved with
// the FFT stages (ILP=2) instead of before them. All lane twiddles hoisted.

typedef unsigned long long u64;

constexpr double PI_D = 3.14159265358979323846264338327950288;

constexpr double d_sin(double x) {
    double t = x, s = x, x2 = x * x;
    for (int n = 1; n <= 11; ++n) { t *= -x2 / double((2*n)*(2*n+1)); s += t; }
    return s;
}
constexpr double d_cos(double x) {
    double t = 1.0, s = 1.0, x2 = x * x;
    for (int n = 1; n <= 11; ++n) { t *= -x2 / double((2*n-1)*(2*n)); s += t; }
    return s;
}
constexpr double d_sqrt(double x) {
    if (x <= 0.0) return 0.0;
    double r = x > 1.0 ? x : 1.0;
    for (int i = 0; i < 40; ++i) r = 0.5 * (r + x / r);
    return r;
}
constexpr double d_i0(double x) {
    double t = 1.0, s = 1.0, q = x * 0.5;
    for (int m = 1; m <= 70; ++m) { double u = q / m; t *= u * u; s += t; }
    return s;
}
constexpr double red(double a) {
    while (a < -PI_D) a += 2.0 * PI_D;
    while (a >  PI_D) a -= 2.0 * PI_D;
    return a;
}
constexpr int bitrev5(int x) {
    return ((x&1)<<4) | ((x&2)<<2) | (x&4) | ((x&8)>>2) | ((x&16)>>4);
}

struct alignas(16) Tab1 {
    float t1r[32][64];   // [k][s]: Re(rw[s]*e^{-2pi i ks/64}) - RKr[k]/64  (hann + mean fold)
    float t1i[32][64];
};
struct alignas(16) Small {
    float tw_r[5][32];   // [stage][lane]: Re(omega32^{(lane&(h-1))*16/h}), h=16>>stage
    float tw_i[5][32];
    float dw[32];        // kaiser(32,25)/sum  (indexed by lane = chirp)
    float wdbr_r[32];    // Re(WD[bitrev5(lane)])/32, WD[d] = FFT(dw)[d]
    float wdbr_i[32];
    float pad[32];
};

constexpr Tab1 make_tab1() {
    Tab1 T{};
    double rw[64] = {}; double rsum = 0.0;
    for (int n = 0; n < 64; ++n) { rw[n] = 0.5 - 0.5 * d_cos(red(2.0*PI_D*n/63.0)); rsum += rw[n]; }
    for (int n = 0; n < 64; ++n) rw[n] /= rsum;
    for (int k = 0; k < 32; ++k) {
        double rkr = 0.0, rki = 0.0;
        for (int s = 0; s < 64; ++s) {
            double ang = red(-2.0*PI_D*double((k*s)&63)/64.0);
            rkr += rw[s]*d_cos(ang); rki += rw[s]*d_sin(ang);
        }
        for (int s = 0; s < 64; ++s) {
            double ang = red(-2.0*PI_D*double((k*s)&63)/64.0);
            T.t1r[k][s] = (float)(rw[s]*d_cos(ang) - rkr/64.0);
            T.t1i[k][s] = (float)(rw[s]*d_sin(ang) - rki/64.0);
        }
    }
    return T;
}
constexpr Small make_small() {
    Small S{};
    for (int st = 0; st < 5; ++st) {
        int h = 16 >> st;
        for (int l = 0; l < 32; ++l) {
            int j = (l & (h - 1)) * (16 / h);
            double ang = red(-2.0*PI_D*j/32.0);
            S.tw_r[st][l] = (float)d_cos(ang);
            S.tw_i[st][l] = (float)d_sin(ang);
        }
    }
    double dw[32] = {}; double dsum = 0.0; double i025 = d_i0(25.0);
    for (int n = 0; n < 32; ++n) {
        double al = 15.5, tt = (n - al) / al, arg = 1.0 - tt*tt;
        dw[n] = d_i0(25.0 * d_sqrt(arg < 0.0 ? 0.0 : arg)) / i025; dsum += dw[n];
    }
    for (int n = 0; n < 32; ++n) dw[n] /= dsum;
    for (int n = 0; n < 32; ++n) S.dw[n] = (float)dw[n];
    for (int l = 0; l < 32; ++l) {
        int d = bitrev5(l);
        double wr = 0.0, wi = 0.0;
        for (int c = 0; c < 32; ++c) {
            double ang = red(-2.0*PI_D*double((d*c)&31)/32.0);
            wr += dw[c]*d_cos(ang); wi += dw[c]*d_sin(ang);
        }
        S.wdbr_r[l] = (float)(wr / 32.0);
        S.wdbr_i[l] = (float)(wi / 32.0);
    }
    return S;
}

__device__ const Tab1  g_tab1  = make_tab1();
__device__ const Small g_small = make_small();

__device__ __forceinline__ void upk(u64 v, float& lo, float& hi) {
    asm("mov.b64 {%0,%1}, %2;" : "=f"(lo), "=f"(hi) : "l"(v));
}
__device__ __forceinline__ u64 ffma2(u64 a, u64 b, u64 c) {
    u64 d; asm("fma.rn.f32x2 %0, %1, %2, %3;" : "=l"(d) : "l"(a), "l"(b), "l"(c)); return d;
}
__device__ __forceinline__ float psum(u64 v) { float lo, hi; upk(v, lo, hi); return lo + hi; }

__global__ __launch_bounds__(32) void rdm_kernel(const float* __restrict__ frame,
                                                 float* __restrict__ out)
{
    const int lane = threadIdx.x;          // chirp c (stage 1) / FFT lane (stage 2)
    const int k    = blockIdx.x;           // range bin

    // ---- hoisted per-lane constants (independent of all other loads) ----
    float twr[5], twi[5];
    #pragma unroll
    for (int st = 0; st < 5; ++st) {
        twr[st] = g_small.tw_r[st][lane];
        twi[st] = g_small.tw_i[st][lane];
    }
    const float dwl  = g_small.dw[lane];
    const float wdr  = g_small.wdbr_r[lane];
    const float wdi  = g_small.wdbr_i[lane];

    // ---- load chirp row c = lane into registers (16 float4, MLP=16) ----
    float4 xv[16];
    {
        const float4* xp = (const float4*)(frame + lane * 64);
        #pragma unroll
        for (int i = 0; i < 16; ++i) xv[i] = xp[i];
    }

    // ---- stage 1: X[k][c] = sum_s x[c][s] * t1[k][s]  (warp-uniform broadcasts) ----
    float Xr, Xi;
    {
        const ulonglong2* tr = (const ulonglong2*)&g_tab1.t1r[k][0];
        const ulonglong2* ti = (const ulonglong2*)&g_tab1.t1i[k][0];
        u64 ar = 0, ai = 0;
        #pragma unroll
        for (int i = 0; i < 16; ++i) {
            u64 x01, x23;
            asm("mov.b64 %0, {%1,%2};" : "=l"(x01) : "f"(xv[i].x), "f"(xv[i].y));
            asm("mov.b64 %0, {%1,%2};" : "=l"(x23) : "f"(xv[i].z), "f"(xv[i].w));
            ulonglong2 tv = tr[i];
            ulonglong2 uv = ti[i];
            ar = ffma2(x01, tv.x, ar);
            ar = ffma2(x23, tv.y, ar);
            ai = ffma2(x01, uv.x, ai);
            ai = ffma2(x23, uv.y, ai);
        }
        Xr = psum(ar);
        Xi = psum(ai);
    }

    // ---- interleaved: mean all-reduce (mr,mi) + FFT of X*dw (vr,vi) ----
    float mr = Xr, mi = Xi;
    float vr = Xr * dwl, vi = Xi * dwl;
    #pragma unroll
    for (int st = 0; st < 5; ++st) {
        const int h = 16 >> st;
        float rr = __shfl_xor_sync(0xFFFFFFFFu, mr, h);
        float ri = __shfl_xor_sync(0xFFFFFFFFu, mi, h);
        float tr = __shfl_xor_sync(0xFFFFFFFFu, vr, h);
        float ti = __shfl_xor_sync(0xFFFFFFFFu, vi, h);
        mr += rr; mi += ri;
        bool up = (lane & h) != 0;
        float sr = vr + tr,  si = vi + ti;    // lower: A + B
        float dr = tr - vr,  di = ti - vi;    // upper: (A - B) * twiddle
        float ur = dr * twr[st] - di * twi[st];
        float ui = dr * twi[st] + di * twr[st];
        vr = up ? ur : sr;
        vi = up ? ui : si;
    }

    // ---- epilogue: Z = F - m*WD (MTI fold); lane holds bin d = bitrev5(lane) ----
    {
        float zr = vr - (mr * wdr - mi * wdi);
        float zi = vi - (mr * wdi + mi * wdr);
        float mag = sqrtf(zr * zr + zi * zi) * 1000.0f;
        float v = fminf(fmaxf(mag, 0.0f), 1.0f) * 255.0f;
        int m = __brev((unsigned)(lane ^ 1)) >> 27;     // (d+16)&31 after fftshift
        out[(31 - k) * 32 + m] = truncf(v);             // one 128B line per CTA
    }
}

extern "C" void kernel_launch(void* const* d_in, const int* in_sizes, int n_in,
                              void* d_out, int out_size)
{
    (void)in_sizes; (void)n_in; (void)out_size;
    rdm_kernel<<<32, 32>>>((const float*)d_in[0], (float*)d_out);
}

// round 17
// speedup vs baseline: 1.3592x; 1.0049x over previous
#include <cuda_runtime.h>

// 32 CTAs x 32 threads (one warp per range bin k). No smem, no barriers.
// Stage 1: lane c holds chirp row c in regs; range DFT vs warp-uniform twiddles.
// Stage 2: kaiser-windowed 32-pt shfl FFT; MTI folded into epilogue.
// Per-lane constants packed into 4x LDG.128; load stream front-batched.

typedef unsigned long long u64;

constexpr double PI_D = 3.14159265358979323846264338327950288;

constexpr double d_sin(double x) {
    double t = x, s = x, x2 = x * x;
    for (int n = 1; n <= 11; ++n) { t *= -x2 / double((2*n)*(2*n+1)); s += t; }
    return s;
}
constexpr double d_cos(double x) {
    double t = 1.0, s = 1.0, x2 = x * x;
    for (int n = 1; n <= 11; ++n) { t *= -x2 / double((2*n-1)*(2*n)); s += t; }
    return s;
}
constexpr double d_sqrt(double x) {
    if (x <= 0.0) return 0.0;
    double r = x > 1.0 ? x : 1.0;
    for (int i = 0; i < 40; ++i) r = 0.5 * (r + x / r);
    return r;
}
constexpr double d_i0(double x) {
    double t = 1.0, s = 1.0, q = x * 0.5;
    for (int m = 1; m <= 70; ++m) { double u = q / m; t *= u * u; s += t; }
    return s;
}
constexpr double red(double a) {
    while (a < -PI_D) a += 2.0 * PI_D;
    while (a >  PI_D) a -= 2.0 * PI_D;
    return a;
}
constexpr int bitrev5(int x) {
    return ((x&1)<<4) | ((x&2)<<2) | (x&4) | ((x&8)>>2) | ((x&16)>>4);
}

struct alignas(16) Tab1 {
    float t1r[32][64];   // [k][s]: Re(rw[s]*e^{-2pi i ks/64}) - RKr[k]/64  (hann + mean fold)
    float t1i[32][64];
};
// Per-lane constants, packed for 4x LDG.128 per lane:
//  q[0] = (twr0, twr1, twr2, twr3)
//  q[1] = (twr4, twi0, twi1, twi2)
//  q[2] = (twi3, twi4, dw,   wdr )
//  q[3] = (wdi,  0,    0,    0   )
struct alignas(16) PerLane {
    float q[32][4][4];
};

constexpr Tab1 make_tab1() {
    Tab1 T{};
    double rw[64] = {}; double rsum = 0.0;
    for (int n = 0; n < 64; ++n) { rw[n] = 0.5 - 0.5 * d_cos(red(2.0*PI_D*n/63.0)); rsum += rw[n]; }
    for (int n = 0; n < 64; ++n) rw[n] /= rsum;
    for (int k = 0; k < 32; ++k) {
        double rkr = 0.0, rki = 0.0;
        for (int s = 0; s < 64; ++s) {
            double ang = red(-2.0*PI_D*double((k*s)&63)/64.0);
            rkr += rw[s]*d_cos(ang); rki += rw[s]*d_sin(ang);
        }
        for (int s = 0; s < 64; ++s) {
            double ang = red(-2.0*PI_D*double((k*s)&63)/64.0);
            T.t1r[k][s] = (float)(rw[s]*d_cos(ang) - rkr/64.0);
            T.t1i[k][s] = (float)(rw[s]*d_sin(ang) - rki/64.0);
        }
    }
    return T;
}
constexpr PerLane make_perlane() {
    PerLane P{};
    double tw_r[5][32] = {}, tw_i[5][32] = {};
    for (int st = 0; st < 5; ++st) {
        int h = 16 >> st;
        for (int l = 0; l < 32; ++l) {
            int j = (l & (h - 1)) * (16 / h);
            double ang = red(-2.0*PI_D*j/32.0);
            tw_r[st][l] = d_cos(ang);
            tw_i[st][l] = d_sin(ang);
        }
    }
    double dw[32] = {}; double dsum = 0.0; double i025 = d_i0(25.0);
    for (int n = 0; n < 32; ++n) {
        double al = 15.5, tt = (n - al) / al, arg = 1.0 - tt*tt;
        dw[n] = d_i0(25.0 * d_sqrt(arg < 0.0 ? 0.0 : arg)) / i025; dsum += dw[n];
    }
    for (int n = 0; n < 32; ++n) dw[n] /= dsum;
    for (int l = 0; l < 32; ++l) {
        int d = bitrev5(l);
        double wr = 0.0, wi = 0.0;
        for (int c = 0; c < 32; ++c) {
            double ang = red(-2.0*PI_D*double((d*c)&31)/32.0);
            wr += dw[c]*d_cos(ang); wi += dw[c]*d_sin(ang);
        }
        P.q[l][0][0] = (float)tw_r[0][l];
        P.q[l][0][1] = (float)tw_r[1][l];
        P.q[l][0][2] = (float)tw_r[2][l];
        P.q[l][0][3] = (float)tw_r[3][l];
        P.q[l][1][0] = (float)tw_r[4][l];
        P.q[l][1][1] = (float)tw_i[0][l];
        P.q[l][1][2] = (float)tw_i[1][l];
        P.q[l][1][3] = (float)tw_i[2][l];
        P.q[l][2][0] = (float)tw_i[3][l];
        P.q[l][2][1] = (float)tw_i[4][l];
        P.q[l][2][2] = (float)dw[l];
        P.q[l][2][3] = (float)(wr / 32.0);
        P.q[l][3][0] = (float)(wi / 32.0);
    }
    return P;
}

__device__ const Tab1    g_tab1 = make_tab1();
__device__ const PerLane g_pl   = make_perlane();

__device__ __forceinline__ void upk(u64 v, float& lo, float& hi) {
    asm("mov.b64 {%0,%1}, %2;" : "=f"(lo), "=f"(hi) : "l"(v));
}
__device__ __forceinline__ u64 ffma2(u64 a, u64 b, u64 c) {
    u64 d; asm("fma.rn.f32x2 %0, %1, %2, %3;" : "=l"(d) : "l"(a), "l"(b), "l"(c)); return d;
}
__device__ __forceinline__ float psum(u64 v) { float lo, hi; upk(v, lo, hi); return lo + hi; }

__global__ __launch_bounds__(32) void rdm_kernel(const float* __restrict__ frame,
                                                 float* __restrict__ out)
{
    const int lane = threadIdx.x;          // chirp c (stage 1) / FFT lane (stage 2)
    const int k    = blockIdx.x;           // range bin

    // ---- front-batched load stream: frame row, per-lane consts, table row ----
    float4 xv[16];
    {
        const float4* xp = (const float4*)(frame + lane * 64);
        #pragma unroll
        for (int i = 0; i < 16; ++i) xv[i] = xp[i];
    }
    float4 q0 = *(const float4*)&g_pl.q[lane][0][0];
    float4 q1 = *(const float4*)&g_pl.q[lane][1][0];
    float4 q2 = *(const float4*)&g_pl.q[lane][2][0];
    float4 q3 = *(const float4*)&g_pl.q[lane][3][0];

    // ---- stage 1: X[k][c] = sum_s x[c][s] * t1[k][s]  (warp-uniform broadcasts) ----
    float Xr, Xi;
    {
        const ulonglong2* tr = (const ulonglong2*)&g_tab1.t1r[k][0];
        const ulonglong2* ti = (const ulonglong2*)&g_tab1.t1i[k][0];
        u64 ar = 0, ai = 0;
        #pragma unroll
        for (int i = 0; i < 16; ++i) {
            u64 x01, x23;
            asm("mov.b64 %0, {%1,%2};" : "=l"(x01) : "f"(xv[i].x), "f"(xv[i].y));
            asm("mov.b64 %0, {%1,%2};" : "=l"(x23) : "f"(xv[i].z), "f"(xv[i].w));
            ulonglong2 tv = tr[i];
            ulonglong2 uv = ti[i];
            ar = ffma2(x01, tv.x, ar);
            ar = ffma2(x23, tv.y, ar);
            ai = ffma2(x01, uv.x, ai);
            ai = ffma2(x23, uv.y, ai);
        }
        Xr = psum(ar);
        Xi = psum(ai);
    }

    const float twr[5] = {q0.x, q0.y, q0.z, q0.w, q1.x};
    const float twi[5] = {q1.y, q1.z, q1.w, q2.x, q2.y};
    const float dwl = q2.z, wdr = q2.w, wdi = q3.x;

    // ---- interleaved: mean all-reduce (mr,mi) + FFT of X*dw (vr,vi) ----
    float mr = Xr, mi = Xi;
    float vr = Xr * dwl, vi = Xi * dwl;
    #pragma unroll
    for (int st = 0; st < 5; ++st) {
        const int h = 16 >> st;
        float rr = __shfl_xor_sync(0xFFFFFFFFu, mr, h);
        float ri = __shfl_xor_sync(0xFFFFFFFFu, mi, h);
        float tr = __shfl_xor_sync(0xFFFFFFFFu, vr, h);
        float ti = __shfl_xor_sync(0xFFFFFFFFu, vi, h);
        mr += rr; mi += ri;
        bool up = (lane & h) != 0;
        float sr = vr + tr,  si = vi + ti;    // lower: A + B
        float dr = tr - vr,  di = ti - vi;    // upper: (A - B) * twiddle
        float ur = dr * twr[st] - di * twi[st];
        float ui = dr * twi[st] + di * twr[st];
        vr = up ? ur : sr;
        vi = up ? ui : si;
    }

    // ---- epilogue: Z = F - m*WD (MTI fold); lane holds bin d = bitrev5(lane) ----
    {
        float zr = vr - (mr * wdr - mi * wdi);
        float zi = vi - (mr * wdi + mi * wdr);
        float mag = sqrtf(zr * zr + zi * zi) * 1000.0f;
        float v = fminf(fmaxf(mag, 0.0f), 1.0f) * 255.0f;
        int m = __brev((unsigned)(lane ^ 1)) >> 27;     // (d+16)&31 after fftshift
        out[(31 - k) * 32 + m] = truncf(v);             // one 128B line per CTA
    }
}

extern "C" void kernel_launch(void* const* d_in, const int* in_sizes, int n_in,
                              void* d_out, int out_size)
{
    (void)in_sizes; (void)n_in; (void)out_size;
    rdm_kernel<<<32, 32>>>((const float*)d_in[0], (float*)d_out);
}